// round 13
// baseline (speedup 1.0000x reference)
#include <cuda_runtime.h>
#include <cstdint>

#define BB   16
#define TT   1024
#define BTN  (BB*TT)      // 16384
#define HH   256
#define WW   128
#define LL   2
#define CC   50
#define FEAT 768

// ---------------- static scratch (no cudaMalloc allowed) ----------------
__device__ float g_h0[(size_t)(BTN+4)*HH];    // padded: h lives at +HH
__device__ float g_h1[(size_t)BTN*HH];
__device__ float g_big[(size_t)BTN*FEAT];     // fused t1|pn|pc [BTN,384]
__device__ float g_t2[(size_t)BTN*WW];
__device__ float g_xx[BTN];
__device__ int   g_idx[BTN*3];
__device__ float g_s2[(size_t)3*BTN*WW];      // planes [3][BTN][128]
__device__ float g_bf[2*384*256];
__device__ float g_bfb[2*384];
__device__ float g_bc[256*768];               // backbone block-diag weights
__device__ float g_cb[2*256];                 // t3b+s3b per layer
__device__ unsigned long long g_ptk[(size_t)BB*8*TT*3];

// ================= helpers =================
__device__ __forceinline__ uint32_t smem_u32(const void* p) {
    uint32_t a;
    asm("{ .reg .u64 t; cvta.to.shared.u64 t, %1; cvt.u32.u64 %0, t; }" : "=r"(a) : "l"(p));
    return a;
}
__device__ __forceinline__ void ldsm4(uint32_t& r0, uint32_t& r1, uint32_t& r2, uint32_t& r3,
                                      uint32_t addr) {
    asm volatile("ldmatrix.sync.aligned.m8n8.x4.shared.b16 {%0,%1,%2,%3}, [%4];"
                 : "=r"(r0), "=r"(r1), "=r"(r2), "=r"(r3) : "r"(addr));
}
__device__ __forceinline__ void mma8(float* c, const uint32_t* a,
                                     uint32_t b0, uint32_t b1) {
    asm volatile("mma.sync.aligned.m16n8k8.row.col.f32.tf32.tf32.f32 "
                 "{%0,%1,%2,%3},{%4,%5,%6,%7},{%8,%9},{%0,%1,%2,%3};"
                 : "+f"(c[0]), "+f"(c[1]), "+f"(c[2]), "+f"(c[3])
                 : "r"(a[0]), "r"(a[1]), "r"(a[2]), "r"(a[3]), "r"(b0), "r"(b1));
}
__device__ __forceinline__ uint32_t cvt_tf32(float x) {
    uint32_t h;
    asm("cvt.rna.tf32.f32 %0, %1;" : "=r"(h) : "f"(x));
    return h;
}
__device__ __forceinline__ uint32_t swz(uint32_t row, uint32_t chunk) {
    return row * 128u + (((chunk ^ (row & 7u)) & 7u) << 4);
}

#define CP16(dst, src, sz) \
    asm volatile("cp.async.cg.shared.global [%0], [%1], 16, %2;" \
                 :: "r"(dst), "l"(src), "r"(sz))
#define CPCOMMIT() asm volatile("cp.async.commit_group;" ::: "memory")
#define CPWAIT2()  asm volatile("cp.async.wait_group 2;" ::: "memory")

// ---- branchless top-3 via sortable 64-bit keys ----
__device__ __forceinline__ unsigned long long t3key(float v, int i) {
    v = v + 0.0f;
    uint32_t b = __float_as_uint(v);
    b = ((int)b < 0) ? ~b : (b | 0x80000000u);
    return ((unsigned long long)b << 32) | (uint32_t)(~i);
}
#define T3K_INS(K)                                                              \
    do {                                                                        \
        unsigned long long _k = (K);                                            \
        unsigned long long _t0 = (k0 > _k) ? _k : k0;                           \
        k0 = (k0 > _k) ? k0 : _k;                                               \
        unsigned long long _t1 = (k1 > _t0) ? _t0 : k1;                         \
        k1 = (k1 > _t0) ? k1 : _t0;                                             \
        k2 = (k2 > _t1) ? k2 : _t1;                                             \
    } while (0)
#define T3K_MERGE(mask)                                                         \
    {                                                                           \
        unsigned long long _a0 = __shfl_xor_sync(0xffffffffu, k0, mask);        \
        unsigned long long _a1 = __shfl_xor_sync(0xffffffffu, k1, mask);        \
        unsigned long long _a2 = __shfl_xor_sync(0xffffffffu, k2, mask);        \
        T3K_INS(_a0); T3K_INS(_a1); T3K_INS(_a2);                               \
    }

// ---- shared MMA fragment helpers (3xTF32 sweep over a stage) ----
#define FRAG_DECLS                                                              \
    const uint32_t rA  = (uint32_t)(warp_m + (lane & 7) + ((lane >> 3) & 1) * 8); \
    const uint32_t cbA = (uint32_t)((lane >> 4) & 1);                           \
    const uint32_t rB  = (uint32_t)(warp_n + (lane & 7) + ((lane >> 4) & 1) * 8); \
    const uint32_t cbB = (uint32_t)((lane >> 3) & 1);                           \
    const uint32_t xA  = (uint32_t)(lane & 7);

#define MMA3_STAGE(s0)                                                        \
    {                                                                         \
        _Pragma("unroll")                                                     \
        for (int s = 0; s < 4; s++) {                                         \
            const uint32_t coA = (((2u * s + cbA) ^ xA) & 7u) << 4;           \
            const uint32_t coB = (((2u * s + cbB) ^ xA) & 7u) << 4;           \
            uint32_t ah[4][4], br[4][2];                                      \
            _Pragma("unroll")                                                 \
            for (int i = 0; i < 4; i++)                                       \
                ldsm4(ah[i][0], ah[i][1], ah[i][2], ah[i][3],                 \
                      (s0) + (rA + 16u * i) * 128u + coA);                    \
            _Pragma("unroll")                                                 \
            for (int p = 0; p < 2; p++)                                       \
                ldsm4(br[2*p][0], br[2*p][1], br[2*p+1][0], br[2*p+1][1],     \
                      (s0) + 16384u + (rB + 16u * p) * 128u + coB);           \
            uint32_t al[4][4], bh[4][2], bl[4][2];                            \
            _Pragma("unroll")                                                 \
            for (int j = 0; j < 4; j++)                                       \
                _Pragma("unroll")                                             \
                for (int q = 0; q < 2; q++) {                                 \
                    float f = __uint_as_float(br[j][q]);                      \
                    uint32_t h = cvt_tf32(f);                                 \
                    bh[j][q] = h;                                             \
                    bl[j][q] = __float_as_uint(f - __uint_as_float(h));       \
                }                                                             \
            _Pragma("unroll")                                                 \
            for (int i = 0; i < 4; i++)                                       \
                _Pragma("unroll")                                             \
                for (int q = 0; q < 4; q++) {                                 \
                    float f = __uint_as_float(ah[i][q]);                      \
                    uint32_t h = cvt_tf32(f);                                 \
                    ah[i][q] = h;                                             \
                    al[i][q] = __float_as_uint(f - __uint_as_float(h));       \
                }                                                             \
            _Pragma("unroll")                                                 \
            for (int i = 0; i < 4; i++)                                       \
                _Pragma("unroll")                                             \
                for (int j = 0; j < 4; j++) {                                 \
                    mma8(acc[i][j], ah[i], bh[j][0], bh[j][1]);               \
                    mma8(acc[i][j], ah[i], bl[j][0], bl[j][1]);               \
                    mma8(acc[i][j], al[i], bh[j][0], bh[j][1]);               \
                }                                                             \
        }                                                                     \
    }

// ============ mma.sync tf32 GEMM: C = act(A[M,K]*B[N,K]^T + bias) ============
template<int TERMS, bool RELU, bool HASBIAS, bool GRAMSYM>
__global__ void __launch_bounds__(256, 1)
mgemm(const float* __restrict__ A, long sA, int lda,
      const float* __restrict__ B, long sB, int ldb,
      const float* __restrict__ bias, int sBias,
      float* __restrict__ C, long sC, int ldc,
      int M, int N, int K, int reluN,
      const float* __restrict__ xx, unsigned long long* __restrict__ ptk)
{
    constexpr int SS    = 32768;
    constexpr int OFF_B = 16384;

    if (GRAMSYM && blockIdx.x < blockIdx.y) return;

    extern __shared__ __align__(1024) char smem[];
    const uint32_t sb = smem_u32(smem);
    float* sbias = (float*)(smem + 4 * SS);

    A += (long)blockIdx.z * sA;
    B += (long)blockIdx.z * sB;
    C += (long)blockIdx.z * sC;
    if (GRAMSYM) {
        xx  += (long)blockIdx.z << 10;
        ptk += (long)blockIdx.z * 8 * TT * 3;
    }
    const int bm = blockIdx.y * 128;
    const int bn = blockIdx.x * 128;

    const int t = threadIdx.x;
    const int lane = t & 31;
    const int wid = t >> 5;
    const int warp_m = (wid & 1) * 64;
    const int warp_n = (wid >> 1) * 32;
    const bool wActive = (bn + warp_n) < N;

    if (HASBIAS && t < 128) {
        const float* bp = bias + (long)blockIdx.z * sBias;
        int n = bn + t;
        sbias[t] = (n < N) ? bp[n] : 0.f;
    }

    uint32_t aOff[4];
    const float* gA[4];
    const float* gB[4];
    uint32_t bSz[4];
#pragma unroll
    for (int i = 0; i < 4; i++) {
        int id = t + 256 * i;
        int row = id >> 3, ch = id & 7;
        aOff[i] = swz((uint32_t)row, (uint32_t)ch);
        gA[i] = A + (long)(bm + row) * lda + ch * 4;
        gB[i] = B + (long)(bn + row) * ldb + ch * 4;
        bSz[i] = ((bn + row) < N) ? 16u : 0u;
    }

#define MG_LOAD(st, kt)                                                       \
    {                                                                         \
        const uint32_t s0 = sb + (uint32_t)(st) * SS;                         \
        _Pragma("unroll")                                                     \
        for (int i = 0; i < 4; i++) {                                         \
            CP16(s0 + aOff[i], gA[i] + (kt) * 32, 16u);                       \
            CP16(s0 + OFF_B + aOff[i], gB[i] + (kt) * 32, bSz[i]);            \
        }                                                                     \
    }

    FRAG_DECLS

    float acc[4][4][4];
#pragma unroll
    for (int i = 0; i < 4; i++)
#pragma unroll
        for (int j = 0; j < 4; j++)
#pragma unroll
            for (int q = 0; q < 4; q++) acc[i][j][q] = 0.f;

#define MG_MMA1(s0)                                                           \
    {                                                                         \
        _Pragma("unroll")                                                     \
        for (int s = 0; s < 4; s++) {                                         \
            const uint32_t coA = (((2u * s + cbA) ^ xA) & 7u) << 4;           \
            const uint32_t coB = (((2u * s + cbB) ^ xA) & 7u) << 4;           \
            uint32_t ah[4][4], br[4][2];                                      \
            _Pragma("unroll")                                                 \
            for (int i = 0; i < 4; i++)                                       \
                ldsm4(ah[i][0], ah[i][1], ah[i][2], ah[i][3],                 \
                      (s0) + (rA + 16u * i) * 128u + coA);                    \
            _Pragma("unroll")                                                 \
            for (int p = 0; p < 2; p++)                                       \
                ldsm4(br[2*p][0], br[2*p][1], br[2*p+1][0], br[2*p+1][1],     \
                      (s0) + 16384u + (rB + 16u * p) * 128u + coB);           \
            _Pragma("unroll")                                                 \
            for (int j = 0; j < 4; j++)                                       \
                _Pragma("unroll")                                             \
                for (int q = 0; q < 2; q++)                                   \
                    br[j][q] = cvt_tf32(__uint_as_float(br[j][q]));           \
            _Pragma("unroll")                                                 \
            for (int i = 0; i < 4; i++)                                       \
                _Pragma("unroll")                                             \
                for (int q = 0; q < 4; q++)                                   \
                    ah[i][q] = cvt_tf32(__uint_as_float(ah[i][q]));           \
            _Pragma("unroll")                                                 \
            for (int i = 0; i < 4; i++)                                       \
                _Pragma("unroll")                                             \
                for (int j = 0; j < 4; j++)                                   \
                    mma8(acc[i][j], ah[i], br[j][0], br[j][1]);               \
        }                                                                     \
    }

    const int nkt = K >> 5;
#pragma unroll
    for (int p = 0; p < 3; p++) {
        if (p < nkt) MG_LOAD(p, p);
        CPCOMMIT();
    }
    for (int kt = 0; kt < nkt; kt++) {
        CPWAIT2();
        __syncthreads();
        const uint32_t s0 = sb + (uint32_t)(kt & 3) * SS;
        if (wActive) {
            if (TERMS == 3) { MMA3_STAGE(s0); }
            else            { MG_MMA1(s0); }
        }
        const int nx = kt + 3;
        if (nx < nkt) MG_LOAD(nx & 3, nx);
        CPCOMMIT();
    }

    if (!GRAMSYM) {
        const int mrow = bm + warp_m + (lane >> 2);
#pragma unroll
        for (int i = 0; i < 4; i++) {
            const int m0 = mrow + i * 16;
            float* C0 = C + (long)m0 * ldc;
            float* C8 = C0 + (long)8 * ldc;
#pragma unroll
            for (int j = 0; j < 4; j++) {
                const int nb = warp_n + j * 8 + (lane & 3) * 2;
                const int nn = bn + nb;
                if (nn >= N) continue;
                float v0 = acc[i][j][0], v1 = acc[i][j][1];
                float v2 = acc[i][j][2], v3 = acc[i][j][3];
                if (HASBIAS) {
                    float b0 = sbias[nb], b1 = sbias[nb + 1];
                    v0 += b0; v1 += b1; v2 += b0; v3 += b1;
                }
                if (RELU && nn < reluN) {
                    v0 = fmaxf(v0, 0.f); v1 = fmaxf(v1, 0.f);
                    v2 = fmaxf(v2, 0.f); v3 = fmaxf(v3, 0.f);
                }
                if ((ldc & 1) == 0) {
                    *(float2*)(C0 + nn) = make_float2(v0, v1);
                    *(float2*)(C8 + nn) = make_float2(v2, v3);
                } else {
                    C0[nn] = v0; C0[nn + 1] = v1;
                    C8[nn] = v2; C8[nn + 1] = v3;
                }
            }
        }
    } else {
        // ---- fused branchless top-3 epilogue, block-merged via smem ----
        __syncthreads();
        float* sxm = (float*)smem;
        float* sxn = sxm + 128;
        unsigned long long* sk = (unsigned long long*)(sxn + 128);
        if (t < 128) { sxm[t] = xx[bm + t]; sxn[t] = xx[bn + t]; }
        __syncthreads();

        const int rbase = warp_m + (lane >> 2);
        const int cbase = warp_n + (lane & 3) * 2;
        const int wn = wid >> 1;
        const int wm = wid & 1;

#pragma unroll
        for (int i = 0; i < 4; i++) {
#pragma unroll
            for (int half = 0; half < 2; half++) {
                unsigned long long k0 = 0ull, k1 = 0ull, k2 = 0ull;
#pragma unroll
                for (int j = 0; j < 4; j++) {
                    const int c0 = cbase + j * 8;
                    T3K_INS(t3key(fmaf(2.f, acc[i][j][half * 2 + 0], -sxn[c0]), bn + c0));
                    T3K_INS(t3key(fmaf(2.f, acc[i][j][half * 2 + 1], -sxn[c0 + 1]), bn + c0 + 1));
                }
                T3K_MERGE(1);
                T3K_MERGE(2);
                if ((lane & 3) == 0) {
                    const int rl = warp_m + (lane >> 2) + i * 16 + half * 8;
                    unsigned long long* d = sk + (rl * 4 + wn) * 3;
                    d[0] = k0; d[1] = k1; d[2] = k2;
                }
            }
        }
        __syncthreads();
        if (t < 128) {
            unsigned long long k0 = 0ull, k1 = 0ull, k2 = 0ull;
#pragma unroll
            for (int w = 0; w < 4; w++) {
                const unsigned long long* d = sk + (t * 4 + w) * 3;
                T3K_INS(d[0]); T3K_INS(d[1]); T3K_INS(d[2]);
            }
            const size_t o = (((size_t)(bn >> 7)) * TT + bm + t) * 3;
            ptk[o] = k0; ptk[o + 1] = k1; ptk[o + 2] = k2;
        }

        if (bm != bn) {
            __syncthreads();
#pragma unroll
            for (int j = 0; j < 4; j++) {
#pragma unroll
                for (int par = 0; par < 2; par++) {
                    unsigned long long k0 = 0ull, k1 = 0ull, k2 = 0ull;
#pragma unroll
                    for (int i = 0; i < 4; i++) {
                        const int r0 = rbase + i * 16;
                        T3K_INS(t3key(fmaf(2.f, acc[i][j][par], -sxm[r0]), bm + r0));
                        T3K_INS(t3key(fmaf(2.f, acc[i][j][par + 2], -sxm[r0 + 8]), bm + r0 + 8));
                    }
                    T3K_MERGE(4);
                    T3K_MERGE(8);
                    T3K_MERGE(16);
                    if ((lane >> 2) == 0) {
                        const int rl = warp_n + (lane & 3) * 2 + j * 8 + par;
                        unsigned long long* d = sk + (rl * 2 + wm) * 3;
                        d[0] = k0; d[1] = k1; d[2] = k2;
                    }
                }
            }
            __syncthreads();
            if (t < 128) {
                unsigned long long k0 = 0ull, k1 = 0ull, k2 = 0ull;
#pragma unroll
                for (int w = 0; w < 2; w++) {
                    const unsigned long long* d = sk + (t * 2 + w) * 3;
                    T3K_INS(d[0]); T3K_INS(d[1]); T3K_INS(d[2]);
                }
                const size_t o = (((size_t)(bm >> 7)) * TT + bn + t) * 3;
                ptk[o] = k0; ptk[o + 1] = k1; ptk[o + 2] = k2;
            }
        }
    }
#undef MG_LOAD
#undef MG_MMA1
}

// ============ planes GEMM: Y = relu(X + t3(t2) + max_k s3(s2_k) + cbias) =====
// 4 K-planes (3x s3w with running max, then t2*t3w summed). M=BTN, N=256, K=128/plane.
__global__ void __launch_bounds__(256, 1)
pgemm(const float* __restrict__ S2, long strideP, const float* __restrict__ T2,
      const float* __restrict__ Ws3, const float* __restrict__ Wt3,
      const float* __restrict__ cbias, const float* __restrict__ Xres,
      float* __restrict__ Y)
{
    constexpr int SS = 32768;
    extern __shared__ __align__(1024) char smem[];
    const uint32_t sb = smem_u32(smem);
    float* sbias = (float*)(smem + 4 * SS);

    const int bm = blockIdx.y * 128;
    const int bn = blockIdx.x * 128;
    const int t = threadIdx.x;
    const int lane = t & 31;
    const int wid = t >> 5;
    const int warp_m = (wid & 1) * 64;
    const int warp_n = (wid >> 1) * 32;

    if (t < 128) sbias[t] = cbias[bn + t];

    uint32_t aOff[4];
    long aG[4], bG[4];
#pragma unroll
    for (int i = 0; i < 4; i++) {
        int id = t + 256 * i;
        int row = id >> 3, ch = id & 7;
        aOff[i] = swz((uint32_t)row, (uint32_t)ch);
        aG[i] = (long)(bm + row) * WW + ch * 4;
        bG[i] = (long)(bn + row) * WW + ch * 4;
    }

#define PG_LOAD(st, f)                                                        \
    {                                                                         \
        const int pl = (f) >> 2;                                              \
        const int kk = (f) & 3;                                               \
        const float* Ab = (pl < 3) ? (S2 + (long)pl * strideP) : T2;          \
        const float* Bb = (pl < 3) ? Ws3 : Wt3;                               \
        const uint32_t s0 = sb + (uint32_t)(st) * SS;                         \
        _Pragma("unroll")                                                     \
        for (int i = 0; i < 4; i++) {                                         \
            CP16(s0 + aOff[i], Ab + aG[i] + kk * 32, 16u);                    \
            CP16(s0 + 16384u + aOff[i], Bb + bG[i] + kk * 32, 16u);           \
        }                                                                     \
    }

    FRAG_DECLS

    float acc[4][4][4], mx[4][4][4];
#pragma unroll
    for (int i = 0; i < 4; i++)
#pragma unroll
        for (int j = 0; j < 4; j++)
#pragma unroll
            for (int q = 0; q < 4; q++) { acc[i][j][q] = 0.f; mx[i][j][q] = -3e38f; }

#pragma unroll
    for (int p = 0; p < 3; p++) { PG_LOAD(p, p); CPCOMMIT(); }
    for (int f = 0; f < 16; f++) {
        CPWAIT2();
        __syncthreads();
        const uint32_t s0 = sb + (uint32_t)(f & 3) * SS;
        MMA3_STAGE(s0);
        if ((f & 3) == 3 && f < 12) {
#pragma unroll
            for (int i = 0; i < 4; i++)
#pragma unroll
                for (int j = 0; j < 4; j++)
#pragma unroll
                    for (int q = 0; q < 4; q++) {
                        mx[i][j][q] = fmaxf(mx[i][j][q], acc[i][j][q]);
                        acc[i][j][q] = 0.f;
                    }
        }
        const int nx = f + 3;
        if (nx < 16) PG_LOAD((nx & 3), nx);
        CPCOMMIT();
    }

    // epilogue: Y = relu(acc(t3) + mx + cbias + X)
    const int mrow = bm + warp_m + (lane >> 2);
#pragma unroll
    for (int i = 0; i < 4; i++) {
        const int m0 = mrow + i * 16;
        const float* X0 = Xres + (long)m0 * HH;
        const float* X8 = X0 + (long)8 * HH;
        float* Y0 = Y + (long)m0 * HH;
        float* Y8 = Y0 + (long)8 * HH;
#pragma unroll
        for (int j = 0; j < 4; j++) {
            const int nb = warp_n + j * 8 + (lane & 3) * 2;
            const int nn = bn + nb;
            float2 x0 = *(const float2*)(X0 + nn);
            float2 x8 = *(const float2*)(X8 + nn);
            float b0 = sbias[nb], b1 = sbias[nb + 1];
            float v0 = acc[i][j][0] + mx[i][j][0] + b0 + x0.x;
            float v1 = acc[i][j][1] + mx[i][j][1] + b1 + x0.y;
            float v2 = acc[i][j][2] + mx[i][j][2] + b0 + x8.x;
            float v3 = acc[i][j][3] + mx[i][j][3] + b1 + x8.y;
            *(float2*)(Y0 + nn) = make_float2(fmaxf(v0, 0.f), fmaxf(v1, 0.f));
            *(float2*)(Y8 + nn) = make_float2(fmaxf(v2, 0.f), fmaxf(v3, 0.f));
        }
    }
#undef PG_LOAD
}

// ---------------- merge per-row key partials into final top-3 indices -------
__global__ void top3_merge(const unsigned long long* __restrict__ ptk,
                           int* __restrict__ idx)
{
    int row = blockIdx.x * 256 + threadIdx.x;
    if (row >= BTN) return;
    int b = row >> 10, r = row & 1023;
    unsigned long long k0 = 0ull, k1 = 0ull, k2 = 0ull;
#pragma unroll
    for (int ct = 0; ct < 8; ct++) {
        size_t o = (((size_t)b * 8 + ct) * TT + r) * 3;
        T3K_INS(ptk[o]); T3K_INS(ptk[o + 1]); T3K_INS(ptk[o + 2]);
    }
    idx[row * 3 + 0] = (int)(~(uint32_t)k0);
    idx[row * 3 + 1] = (int)(~(uint32_t)k1);
    idx[row * 3 + 2] = (int)(~(uint32_t)k2);
}

// ---------------- pack fused B + combined bias for BOTH layers --------------
__global__ void pack_fused2(const float* __restrict__ t1w, const float* __restrict__ t1b,
                            const float* __restrict__ s1w, const float* __restrict__ s1b,
                            const float* __restrict__ t3b, const float* __restrict__ s3b,
                            float* __restrict__ Bf, float* __restrict__ bf,
                            float* __restrict__ cb)
{
    const int l = blockIdx.y;
    const float* t1wl = t1w + (size_t)l * WW * HH;
    const float* t1bl = t1b + (size_t)l * WW;
    const float* s1wl = s1w + (size_t)l * WW * (2 * HH);
    const float* s1bl = s1b + (size_t)l * WW;
    float* B = Bf + (size_t)l * 384 * 256;
    float* bb = bf + (size_t)l * 384;
    int i = blockIdx.x * 256 + threadIdx.x;
    if (i < 384 * 256) {
        int r = i >> 8, c = i & 255;
        float v;
        if (r < 128)      v = t1wl[r * 256 + c];
        else if (r < 256) v = s1wl[(r - 128) * 512 + c];
        else              v = s1wl[(r - 256) * 512 + 256 + c];
        B[i] = v;
    }
    if (i < 384)
        bb[i] = (i < 128) ? t1bl[i] : (i < 256 ? 0.f : s1bl[i - 256]);
    if (i < 256)
        cb[l * 256 + i] = t3b[l * 256 + i] + s3b[l * 256 + i];
}

// ---------------- pack backbone block-diagonal weights [256][768] ------------
__global__ void pack_conv(const float* __restrict__ w, float* __restrict__ Bc)
{
    int idx = blockIdx.x * 256 + threadIdx.x;
    if (idx >= 256 * 768) return;
    int o = idx / 768, k = idx % 768;
    int dt = k >> 8, c = k & 255;
    int g = o >> 6;
    float v = 0.f;
    if ((c >> 6) == g) v = w[o * 192 + (c & 63) * 3 + dt];
    Bc[idx] = v;
}

// ---------------- backbone boundary fixup (rows t=0 and t=1023) --------------
__global__ void conv_fixup(const float* __restrict__ h, const float* __restrict__ w,
                           const float* __restrict__ cb, float* __restrict__ out)
{
    int b = blockIdx.x >> 1;
    int t = (blockIdx.x & 1) ? (TT - 1) : 0;
    int o = threadIdx.x;
    int g = o >> 6;
    float acc = cb[o];
#pragma unroll
    for (int dt = 0; dt < 3; dt++) {
        int ts = t + dt - 1;
        if (ts < 0 || ts >= TT) continue;
        const float* hr = h + ((size_t)(b << 10) + ts) * HH + g * 64;
#pragma unroll
        for (int i = 0; i < 64; i++)
            acc = fmaf(w[o * 192 + i * 3 + dt], hr[i], acc);
    }
    out[((size_t)(b << 10) + t) * HH + o] = fmaxf(acc, 0.f);
}

// ---------------- t2: grouped conv1d (groups=32, 4 in/group, k=3), relu ------
__global__ void t2conv(const float* __restrict__ x, int ldx,
                       const float* __restrict__ w,
                       const float* __restrict__ bias, float* __restrict__ y)
{
    __shared__ float sh[34][WW];
    const int b  = blockIdx.y;
    const int t0 = blockIdx.x * 32;
    const int o  = threadIdx.x;

#pragma unroll 2
    for (int r = 0; r < 34; r++) {
        int ts = t0 - 1 + r;
        sh[r][o] = (ts >= 0 && ts < TT) ? x[(((size_t)b << 10) + ts) * ldx + o] : 0.f;
    }
    __syncthreads();

    float wr[12];
#pragma unroll
    for (int q = 0; q < 12; q++) wr[q] = w[o * 12 + q];
    const float bb = bias[o];
    const int g4 = (o >> 2) << 2;

    for (int tt = 0; tt < 32; tt++) {
        float acc = bb;
#pragma unroll
        for (int i = 0; i < 4; i++)
#pragma unroll
            for (int dt = 0; dt < 3; dt++)
                acc = fmaf(wr[i * 3 + dt], sh[tt + dt][g4 + i], acc);
        y[(((size_t)b << 10) + t0 + tt) * WW + o] = fmaxf(acc, 0.f);
    }
}

// ---------------- per-frame squared L2 norms ----------------
__global__ void rownorm(const float* __restrict__ X, float* __restrict__ xx)
{
    int row = blockIdx.x * 8 + (threadIdx.x >> 5);
    int lane = threadIdx.x & 31;
    const float* p = X + (size_t)row * HH;
    float s = 0.f;
#pragma unroll
    for (int c = lane; c < HH; c += 32) { float v = p[c]; s = fmaf(v, v, s); }
#pragma unroll
    for (int off = 16; off; off >>= 1) s += __shfl_down_sync(0xffffffffu, s, off);
    if (!lane) xx[row] = s;
}

// ---------------- fused s1-epilogue (gather+relu) + grouped s2, plane out ----
__global__ void s1s2(const float* __restrict__ Pn, const float* __restrict__ Pc, int ld,
                     const int* __restrict__ idx, const float* __restrict__ s2w,
                     const float* __restrict__ s2b, float* __restrict__ out)
{
    const int bt = blockIdx.x;
    const int c  = threadIdx.x;
    const int b  = bt >> 10;
    __shared__ float sh[3][WW];
    __shared__ int sidx[3];
    if (c < 3) sidx[c] = idx[bt * 3 + c];
    __syncthreads();

    const float pc = Pc[(size_t)bt * ld + c];
#pragma unroll
    for (int k = 0; k < 3; k++) {
        size_t j = ((size_t)(b << 10) + sidx[k]);
        sh[k][c] = fmaxf(Pn[j * ld + c] + pc, 0.f);
    }
    __syncthreads();

    const float w0 = s2w[c * 4 + 0], w1 = s2w[c * 4 + 1];
    const float w2 = s2w[c * 4 + 2], w3 = s2w[c * 4 + 3];
    const float bb = s2b[c];
    const int gb = (c >> 2) << 2;
#pragma unroll
    for (int k = 0; k < 3; k++) {
        float acc = bb;
        acc = fmaf(w0, sh[k][gb + 0], acc);
        acc = fmaf(w1, sh[k][gb + 1], acc);
        acc = fmaf(w2, sh[k][gb + 2], acc);
        acc = fmaf(w3, sh[k][gb + 3], acc);
        out[((size_t)k * BTN + bt) * WW + c] = fmaxf(acc, 0.f);
    }
}

// ---------------- host side ----------------
static const int SHM = 4 * 32768 + 1024;

template<int TERMS, bool RELU, bool HASBIAS, bool GRAMSYM>
static void launch_mgemm(dim3 grid,
                         const float* A, long sA, int lda,
                         const float* B, long sB, int ldb,
                         const float* bias, int sBias,
                         float* C, long sC, int ldc,
                         int M, int N, int K, int reluN,
                         const float* xx, unsigned long long* ptk)
{
    static bool init = [] {
        cudaFuncSetAttribute(mgemm<TERMS, RELU, HASBIAS, GRAMSYM>,
                             cudaFuncAttributeMaxDynamicSharedMemorySize, SHM);
        return true;
    }();
    (void)init;
    mgemm<TERMS, RELU, HASBIAS, GRAMSYM><<<grid, 256, SHM>>>(
        A, sA, lda, B, sB, ldb, bias, sBias, C, sC, ldc, M, N, K, reluN, xx, ptk);
}

static void tgemm(const float* A, long sA, int lda,
                  const float* B, long sB, int ldb,
                  const float* bias, int sBias,
                  float* C, long sC, int ldc,
                  int M, int N, int K, int batches, bool relu, int reluN,
                  int terms)
{
    dim3 grid((N + 127) / 128, M / 128, batches);
    if (terms == 3) {
        if (relu)
            launch_mgemm<3, true, true, false>(grid, A, sA, lda, B, sB, ldb, bias, sBias,
                                               C, sC, ldc, M, N, K, reluN, nullptr, nullptr);
        else if (bias)
            launch_mgemm<3, false, true, false>(grid, A, sA, lda, B, sB, ldb, bias, sBias,
                                                C, sC, ldc, M, N, K, 0, nullptr, nullptr);
        else
            launch_mgemm<3, false, false, false>(grid, A, sA, lda, B, sB, ldb, nullptr, 0,
                                                 C, sC, ldc, M, N, K, 0, nullptr, nullptr);
    } else {
        launch_mgemm<1, false, true, false>(grid, A, sA, lda, B, sB, ldb, bias, sBias,
                                            C, sC, ldc, M, N, K, 0, nullptr, nullptr);
    }
}

extern "C" void kernel_launch(void* const* d_in, const int* in_sizes, int n_in,
                              void* d_out, int out_size)
{
    const float* x      = (const float*)d_in[0];
    const float* fcin_w = (const float*)d_in[1];
    const float* fcin_b = (const float*)d_in[2];
    const float* conv_w = (const float*)d_in[3];
    const float* conv_b = (const float*)d_in[4];
    const float* t1w    = (const float*)d_in[5];
    const float* t1b    = (const float*)d_in[6];
    const float* t2w    = (const float*)d_in[7];
    const float* t2b    = (const float*)d_in[8];
    const float* t3w    = (const float*)d_in[9];
    const float* t3b    = (const float*)d_in[10];
    const float* s1w    = (const float*)d_in[11];
    const float* s1b    = (const float*)d_in[12];
    const float* s2w    = (const float*)d_in[13];
    const float* s2b    = (const float*)d_in[14];
    const float* s3w    = (const float*)d_in[15];
    const float* s3b    = (const float*)d_in[16];
    const float* fcw    = (const float*)d_in[17];
    const float* fcb    = (const float*)d_in[18];

    void *vp;
    float *p_h0, *p_h1, *p_big, *p_t2, *p_xx, *p_s2, *p_bf, *p_bfb, *p_bc, *p_cb;
    unsigned long long* p_ptk;
    int *p_idx;
    cudaGetSymbolAddress(&vp, g_h0);   p_h0   = (float*)vp;
    cudaGetSymbolAddress(&vp, g_h1);   p_h1   = (float*)vp;
    cudaGetSymbolAddress(&vp, g_big);  p_big  = (float*)vp;
    cudaGetSymbolAddress(&vp, g_t2);   p_t2   = (float*)vp;
    cudaGetSymbolAddress(&vp, g_xx);   p_xx   = (float*)vp;
    cudaGetSymbolAddress(&vp, g_idx);  p_idx  = (int*)vp;
    cudaGetSymbolAddress(&vp, g_s2);   p_s2   = (float*)vp;
    cudaGetSymbolAddress(&vp, g_bf);   p_bf   = (float*)vp;
    cudaGetSymbolAddress(&vp, g_bfb);  p_bfb  = (float*)vp;
    cudaGetSymbolAddress(&vp, g_bc);   p_bc   = (float*)vp;
    cudaGetSymbolAddress(&vp, g_cb);   p_cb   = (float*)vp;
    cudaGetSymbolAddress(&vp, g_ptk);  p_ptk  = (unsigned long long*)vp;

    float* h = p_h0 + HH;   // padded h base

    // 0) weight packs
    pack_fused2<<<dim3(384, 2), 256>>>(t1w, t1b, s1w, s1b, t3b, s3b, p_bf, p_bfb, p_cb);
    pack_conv<<<768, 256>>>(conv_w, p_bc);

    // 1) fc_in + relu -> h (padded base)
    tgemm(x, 0, FEAT, fcin_w, 0, FEAT, fcin_b, 0, h, 0, HH, BTN, HH, FEAT, 1, true, HH, 3);

    // 2) backbone conv as shifted-window GEMM (A = h-256) + boundary fixup
    tgemm(p_h0, 0, HH, p_bc, 0, 768, conv_b, 0, p_h1, 0, HH, BTN, HH, 768, 1, true, HH, 3);
    conv_fixup<<<32, 256>>>(h, conv_w, conv_b, p_h1);

    // 3) GCNeXt blocks
    {
        static bool init = [] {
            cudaFuncSetAttribute(pgemm, cudaFuncAttributeMaxDynamicSharedMemorySize, SHM);
            return true;
        }();
        (void)init;
    }
    for (int l = 0; l < LL; l++) {
        const float* X = (l == 0) ? p_h1 : p_h0;
        float*       Y = (l == 0) ? p_h0 : p_h1;
        const float* t3wl = t3w + (size_t)l * HH * WW;
        const float* s3wl = s3w + (size_t)l * HH * WW;

        // fused t1|Pn|Pc GEMM: N=384, relu only on first 128 cols
        tgemm(X, 0, HH, p_bf + (size_t)l * 384 * 256, 0, HH, p_bfb + (size_t)l * 384, 0,
              p_big, 0, 384, BTN, 384, HH, 1, true, 128, 3);

        t2conv<<<dim3(TT / 32, BB), WW>>>(p_big, 384, t2w + (size_t)l * WW * 12,
                                          t2b + (size_t)l * WW, p_t2);

        // kNN graph: symmetric gram with fused branchless top-3
        rownorm<<<BTN / 8, 256>>>(X, p_xx);
        {
            dim3 grid(8, 8, BB);
            launch_mgemm<3, false, false, true>(grid,
                X, (long)TT * HH, HH, X, (long)TT * HH, HH, nullptr, 0,
                nullptr, 0, 0, TT, TT, HH, 0, p_xx, p_ptk);
        }
        top3_merge<<<(BTN + 255) / 256, 256>>>(p_ptk, p_idx);

        // semantic branch: gather -> s2 planes
        s1s2<<<BTN, WW>>>(p_big + 128, p_big + 256, 384, p_idx,
                          s2w + (size_t)l * WW * 4, s2b + (size_t)l * WW, p_s2);

        // fused t3 + s3-max + residual + relu
        pgemm<<<dim3(2, BTN / 128), 256, SHM>>>(
            p_s2, (long)BTN * WW, p_t2, s3wl, t3wl, p_cb + (size_t)l * 256, X, Y);
    }

    // 4) final fc
    tgemm(p_h1, 0, HH, fcw, 0, HH, fcb, 0, (float*)d_out, 0, CC, BTN, CC, HH, 1, false, 0, 1);
}

// round 14
// speedup vs baseline: 1.0870x; 1.0870x over previous
#include <cuda_runtime.h>
#include <cstdint>

#define BB   16
#define TT   1024
#define BTN  (BB*TT)      // 16384
#define HH   256
#define WW   128
#define LL   2
#define CC   50
#define FEAT 768

// ---------------- static scratch (no cudaMalloc allowed) ----------------
__device__ float g_h0[(size_t)BTN*HH];
__device__ float g_h1[(size_t)BTN*HH];
__device__ float g_big[(size_t)BTN*FEAT];     // im2col, later fused t1|pn|pc [BTN,384]
__device__ float g_t2[(size_t)BTN*WW];
__device__ float g_xx[BTN];
__device__ int   g_idx[BTN*3];
__device__ float g_s2[(size_t)3*BTN*WW];      // planes [3][BTN][128]
__device__ float g_bf[2*384*256];
__device__ float g_bfb[2*384];
__device__ float g_cb[2*256];                 // t3b+s3b per layer
__device__ unsigned long long g_ptk[(size_t)BB*8*TT*3];

// ================= helpers =================
__device__ __forceinline__ uint32_t smem_u32(const void* p) {
    uint32_t a;
    asm("{ .reg .u64 t; cvta.to.shared.u64 t, %1; cvt.u32.u64 %0, t; }" : "=r"(a) : "l"(p));
    return a;
}
__device__ __forceinline__ void ldsm4(uint32_t& r0, uint32_t& r1, uint32_t& r2, uint32_t& r3,
                                      uint32_t addr) {
    asm volatile("ldmatrix.sync.aligned.m8n8.x4.shared.b16 {%0,%1,%2,%3}, [%4];"
                 : "=r"(r0), "=r"(r1), "=r"(r2), "=r"(r3) : "r"(addr));
}
__device__ __forceinline__ void mma8(float* c, const uint32_t* a,
                                     uint32_t b0, uint32_t b1) {
    asm volatile("mma.sync.aligned.m16n8k8.row.col.f32.tf32.tf32.f32 "
                 "{%0,%1,%2,%3},{%4,%5,%6,%7},{%8,%9},{%0,%1,%2,%3};"
                 : "+f"(c[0]), "+f"(c[1]), "+f"(c[2]), "+f"(c[3])
                 : "r"(a[0]), "r"(a[1]), "r"(a[2]), "r"(a[3]), "r"(b0), "r"(b1));
}
__device__ __forceinline__ uint32_t cvt_tf32(float x) {
    uint32_t h;
    asm("cvt.rna.tf32.f32 %0, %1;" : "=r"(h) : "f"(x));
    return h;
}
__device__ __forceinline__ uint32_t swz(uint32_t row, uint32_t chunk) {
    return row * 128u + (((chunk ^ (row & 7u)) & 7u) << 4);
}

#define CP16(dst, src, sz) \
    asm volatile("cp.async.cg.shared.global [%0], [%1], 16, %2;" \
                 :: "r"(dst), "l"(src), "r"(sz))
#define CPCOMMIT() asm volatile("cp.async.commit_group;" ::: "memory")
#define CPWAIT2()  asm volatile("cp.async.wait_group 2;" ::: "memory")

// ---- branchless top-3 via sortable 64-bit keys ----
__device__ __forceinline__ unsigned long long t3key(float v, int i) {
    v = v + 0.0f;
    uint32_t b = __float_as_uint(v);
    b = ((int)b < 0) ? ~b : (b | 0x80000000u);
    return ((unsigned long long)b << 32) | (uint32_t)(~i);
}
#define T3K_INS(K)                                                              \
    do {                                                                        \
        unsigned long long _k = (K);                                            \
        unsigned long long _t0 = (k0 > _k) ? _k : k0;                           \
        k0 = (k0 > _k) ? k0 : _k;                                               \
        unsigned long long _t1 = (k1 > _t0) ? _t0 : k1;                         \
        k1 = (k1 > _t0) ? k1 : _t0;                                             \
        k2 = (k2 > _t1) ? k2 : _t1;                                             \
    } while (0)
#define T3K_MERGE(mask)                                                         \
    {                                                                           \
        unsigned long long _a0 = __shfl_xor_sync(0xffffffffu, k0, mask);        \
        unsigned long long _a1 = __shfl_xor_sync(0xffffffffu, k1, mask);        \
        unsigned long long _a2 = __shfl_xor_sync(0xffffffffu, k2, mask);        \
        T3K_INS(_a0); T3K_INS(_a1); T3K_INS(_a2);                               \
    }

// ---- shared MMA fragment helpers (3xTF32 sweep over a stage) ----
#define FRAG_DECLS                                                              \
    const uint32_t rA  = (uint32_t)(warp_m + (lane & 7) + ((lane >> 3) & 1) * 8); \
    const uint32_t cbA = (uint32_t)((lane >> 4) & 1);                           \
    const uint32_t rB  = (uint32_t)(warp_n + (lane & 7) + ((lane >> 4) & 1) * 8); \
    const uint32_t cbB = (uint32_t)((lane >> 3) & 1);                           \
    const uint32_t xA  = (uint32_t)(lane & 7);

#define MMA3_STAGE(s0)                                                        \
    {                                                                         \
        _Pragma("unroll")                                                     \
        for (int s = 0; s < 4; s++) {                                         \
            const uint32_t coA = (((2u * s + cbA) ^ xA) & 7u) << 4;           \
            const uint32_t coB = (((2u * s + cbB) ^ xA) & 7u) << 4;           \
            uint32_t ah[4][4], br[4][2];                                      \
            _Pragma("unroll")                                                 \
            for (int i = 0; i < 4; i++)                                       \
                ldsm4(ah[i][0], ah[i][1], ah[i][2], ah[i][3],                 \
                      (s0) + (rA + 16u * i) * 128u + coA);                    \
            _Pragma("unroll")                                                 \
            for (int p = 0; p < 2; p++)                                       \
                ldsm4(br[2*p][0], br[2*p][1], br[2*p+1][0], br[2*p+1][1],     \
                      (s0) + 16384u + (rB + 16u * p) * 128u + coB);           \
            uint32_t al[4][4], bh[4][2], bl[4][2];                            \
            _Pragma("unroll")                                                 \
            for (int j = 0; j < 4; j++)                                       \
                _Pragma("unroll")                                             \
                for (int q = 0; q < 2; q++) {                                 \
                    float f = __uint_as_float(br[j][q]);                      \
                    uint32_t h = cvt_tf32(f);                                 \
                    bh[j][q] = h;                                             \
                    bl[j][q] = __float_as_uint(f - __uint_as_float(h));       \
                }                                                             \
            _Pragma("unroll")                                                 \
            for (int i = 0; i < 4; i++)                                       \
                _Pragma("unroll")                                             \
                for (int q = 0; q < 4; q++) {                                 \
                    float f = __uint_as_float(ah[i][q]);                      \
                    uint32_t h = cvt_tf32(f);                                 \
                    ah[i][q] = h;                                             \
                    al[i][q] = __float_as_uint(f - __uint_as_float(h));       \
                }                                                             \
            _Pragma("unroll")                                                 \
            for (int i = 0; i < 4; i++)                                       \
                _Pragma("unroll")                                             \
                for (int j = 0; j < 4; j++) {                                 \
                    mma8(acc[i][j], ah[i], bh[j][0], bh[j][1]);               \
                    mma8(acc[i][j], ah[i], bl[j][0], bl[j][1]);               \
                    mma8(acc[i][j], al[i], bh[j][0], bh[j][1]);               \
                }                                                             \
        }                                                                     \
    }

// ============ mma.sync tf32 GEMM: C = act(A[M,K]*B[N,K]^T + bias) ============
template<int TERMS, bool RELU, bool HASBIAS, bool GRAMSYM>
__global__ void __launch_bounds__(256, 1)
mgemm(const float* __restrict__ A, long sA, int lda,
      const float* __restrict__ B, long sB, int ldb,
      const float* __restrict__ bias, int sBias,
      float* __restrict__ C, long sC, int ldc,
      int M, int N, int K, int reluN,
      const float* __restrict__ xx, unsigned long long* __restrict__ ptk)
{
    constexpr int SS    = 32768;
    constexpr int OFF_B = 16384;

    if (GRAMSYM && blockIdx.x < blockIdx.y) return;

    extern __shared__ __align__(1024) char smem[];
    const uint32_t sb = smem_u32(smem);
    float* sbias = (float*)(smem + 4 * SS);

    A += (long)blockIdx.z * sA;
    B += (long)blockIdx.z * sB;
    C += (long)blockIdx.z * sC;
    if (GRAMSYM) {
        xx  += (long)blockIdx.z << 10;
        ptk += (long)blockIdx.z * 8 * TT * 3;
    }
    const int bm = blockIdx.y * 128;
    const int bn = blockIdx.x * 128;

    const int t = threadIdx.x;
    const int lane = t & 31;
    const int wid = t >> 5;
    const int warp_m = (wid & 1) * 64;
    const int warp_n = (wid >> 1) * 32;
    const bool wActive = (bn + warp_n) < N;

    if (HASBIAS && t < 128) {
        const float* bp = bias + (long)blockIdx.z * sBias;
        int n = bn + t;
        sbias[t] = (n < N) ? bp[n] : 0.f;
    }

    uint32_t aOff[4];
    const float* gA[4];
    const float* gB[4];
    uint32_t bSz[4];
#pragma unroll
    for (int i = 0; i < 4; i++) {
        int id = t + 256 * i;
        int row = id >> 3, ch = id & 7;
        aOff[i] = swz((uint32_t)row, (uint32_t)ch);
        gA[i] = A + (long)(bm + row) * lda + ch * 4;
        gB[i] = B + (long)(bn + row) * ldb + ch * 4;
        bSz[i] = ((bn + row) < N) ? 16u : 0u;
    }

#define MG_LOAD(st, kt)                                                       \
    {                                                                         \
        const uint32_t s0 = sb + (uint32_t)(st) * SS;                         \
        _Pragma("unroll")                                                     \
        for (int i = 0; i < 4; i++) {                                         \
            CP16(s0 + aOff[i], gA[i] + (kt) * 32, 16u);                       \
            CP16(s0 + OFF_B + aOff[i], gB[i] + (kt) * 32, bSz[i]);            \
        }                                                                     \
    }

    FRAG_DECLS

    float acc[4][4][4];
#pragma unroll
    for (int i = 0; i < 4; i++)
#pragma unroll
        for (int j = 0; j < 4; j++)
#pragma unroll
            for (int q = 0; q < 4; q++) acc[i][j][q] = 0.f;

#define MG_MMA1(s0)                                                           \
    {                                                                         \
        _Pragma("unroll")                                                     \
        for (int s = 0; s < 4; s++) {                                         \
            const uint32_t coA = (((2u * s + cbA) ^ xA) & 7u) << 4;           \
            const uint32_t coB = (((2u * s + cbB) ^ xA) & 7u) << 4;           \
            uint32_t ah[4][4], br[4][2];                                      \
            _Pragma("unroll")                                                 \
            for (int i = 0; i < 4; i++)                                       \
                ldsm4(ah[i][0], ah[i][1], ah[i][2], ah[i][3],                 \
                      (s0) + (rA + 16u * i) * 128u + coA);                    \
            _Pragma("unroll")                                                 \
            for (int p = 0; p < 2; p++)                                       \
                ldsm4(br[2*p][0], br[2*p][1], br[2*p+1][0], br[2*p+1][1],     \
                      (s0) + 16384u + (rB + 16u * p) * 128u + coB);           \
            _Pragma("unroll")                                                 \
            for (int j = 0; j < 4; j++)                                       \
                _Pragma("unroll")                                             \
                for (int q = 0; q < 2; q++)                                   \
                    br[j][q] = cvt_tf32(__uint_as_float(br[j][q]));           \
            _Pragma("unroll")                                                 \
            for (int i = 0; i < 4; i++)                                       \
                _Pragma("unroll")                                             \
                for (int q = 0; q < 4; q++)                                   \
                    ah[i][q] = cvt_tf32(__uint_as_float(ah[i][q]));           \
            _Pragma("unroll")                                                 \
            for (int i = 0; i < 4; i++)                                       \
                _Pragma("unroll")                                             \
                for (int j = 0; j < 4; j++)                                   \
                    mma8(acc[i][j], ah[i], br[j][0], br[j][1]);               \
        }                                                                     \
    }

    const int nkt = K >> 5;
#pragma unroll
    for (int p = 0; p < 3; p++) {
        if (p < nkt) MG_LOAD(p, p);
        CPCOMMIT();
    }
    for (int kt = 0; kt < nkt; kt++) {
        CPWAIT2();
        __syncthreads();
        const uint32_t s0 = sb + (uint32_t)(kt & 3) * SS;
        if (wActive) {
            if (TERMS == 3) { MMA3_STAGE(s0); }
            else            { MG_MMA1(s0); }
        }
        const int nx = kt + 3;
        if (nx < nkt) MG_LOAD(nx & 3, nx);
        CPCOMMIT();
    }

    if (!GRAMSYM) {
        const int mrow = bm + warp_m + (lane >> 2);
#pragma unroll
        for (int i = 0; i < 4; i++) {
            const int m0 = mrow + i * 16;
            float* C0 = C + (long)m0 * ldc;
            float* C8 = C0 + (long)8 * ldc;
#pragma unroll
            for (int j = 0; j < 4; j++) {
                const int nb = warp_n + j * 8 + (lane & 3) * 2;
                const int nn = bn + nb;
                if (nn >= N) continue;
                float v0 = acc[i][j][0], v1 = acc[i][j][1];
                float v2 = acc[i][j][2], v3 = acc[i][j][3];
                if (HASBIAS) {
                    float b0 = sbias[nb], b1 = sbias[nb + 1];
                    v0 += b0; v1 += b1; v2 += b0; v3 += b1;
                }
                if (RELU && nn < reluN) {
                    v0 = fmaxf(v0, 0.f); v1 = fmaxf(v1, 0.f);
                    v2 = fmaxf(v2, 0.f); v3 = fmaxf(v3, 0.f);
                }
                if ((ldc & 1) == 0) {
                    *(float2*)(C0 + nn) = make_float2(v0, v1);
                    *(float2*)(C8 + nn) = make_float2(v2, v3);
                } else {
                    C0[nn] = v0; C0[nn + 1] = v1;
                    C8[nn] = v2; C8[nn + 1] = v3;
                }
            }
        }
    } else {
        // ---- fused branchless top-3 epilogue, block-merged via smem ----
        __syncthreads();
        float* sxm = (float*)smem;
        float* sxn = sxm + 128;
        unsigned long long* sk = (unsigned long long*)(sxn + 128);
        if (t < 128) { sxm[t] = xx[bm + t]; sxn[t] = xx[bn + t]; }
        __syncthreads();

        const int rbase = warp_m + (lane >> 2);
        const int cbase = warp_n + (lane & 3) * 2;
        const int wn = wid >> 1;
        const int wm = wid & 1;

#pragma unroll
        for (int i = 0; i < 4; i++) {
#pragma unroll
            for (int half = 0; half < 2; half++) {
                unsigned long long k0 = 0ull, k1 = 0ull, k2 = 0ull;
#pragma unroll
                for (int j = 0; j < 4; j++) {
                    const int c0 = cbase + j * 8;
                    T3K_INS(t3key(fmaf(2.f, acc[i][j][half * 2 + 0], -sxn[c0]), bn + c0));
                    T3K_INS(t3key(fmaf(2.f, acc[i][j][half * 2 + 1], -sxn[c0 + 1]), bn + c0 + 1));
                }
                T3K_MERGE(1);
                T3K_MERGE(2);
                if ((lane & 3) == 0) {
                    const int rl = warp_m + (lane >> 2) + i * 16 + half * 8;
                    unsigned long long* d = sk + (rl * 4 + wn) * 3;
                    d[0] = k0; d[1] = k1; d[2] = k2;
                }
            }
        }
        __syncthreads();
        if (t < 128) {
            unsigned long long k0 = 0ull, k1 = 0ull, k2 = 0ull;
#pragma unroll
            for (int w = 0; w < 4; w++) {
                const unsigned long long* d = sk + (t * 4 + w) * 3;
                T3K_INS(d[0]); T3K_INS(d[1]); T3K_INS(d[2]);
            }
            const size_t o = (((size_t)(bn >> 7)) * TT + bm + t) * 3;
            ptk[o] = k0; ptk[o + 1] = k1; ptk[o + 2] = k2;
        }

        if (bm != bn) {
            __syncthreads();
#pragma unroll
            for (int j = 0; j < 4; j++) {
#pragma unroll
                for (int par = 0; par < 2; par++) {
                    unsigned long long k0 = 0ull, k1 = 0ull, k2 = 0ull;
#pragma unroll
                    for (int i = 0; i < 4; i++) {
                        const int r0 = rbase + i * 16;
                        T3K_INS(t3key(fmaf(2.f, acc[i][j][par], -sxm[r0]), bm + r0));
                        T3K_INS(t3key(fmaf(2.f, acc[i][j][par + 2], -sxm[r0 + 8]), bm + r0 + 8));
                    }
                    T3K_MERGE(4);
                    T3K_MERGE(8);
                    T3K_MERGE(16);
                    if ((lane >> 2) == 0) {
                        const int rl = warp_n + (lane & 3) * 2 + j * 8 + par;
                        unsigned long long* d = sk + (rl * 2 + wm) * 3;
                        d[0] = k0; d[1] = k1; d[2] = k2;
                    }
                }
            }
            __syncthreads();
            if (t < 128) {
                unsigned long long k0 = 0ull, k1 = 0ull, k2 = 0ull;
#pragma unroll
                for (int w = 0; w < 2; w++) {
                    const unsigned long long* d = sk + (t * 2 + w) * 3;
                    T3K_INS(d[0]); T3K_INS(d[1]); T3K_INS(d[2]);
                }
                const size_t o = (((size_t)(bm >> 7)) * TT + bn + t) * 3;
                ptk[o] = k0; ptk[o + 1] = k1; ptk[o + 2] = k2;
            }
        }
    }
#undef MG_LOAD
#undef MG_MMA1
}

// ============ planes GEMM: Y = relu(X + t3(t2) + max_k s3(s2_k) + cbias) =====
__global__ void __launch_bounds__(256, 1)
pgemm(const float* __restrict__ S2, long strideP, const float* __restrict__ T2,
      const float* __restrict__ Ws3, const float* __restrict__ Wt3,
      const float* __restrict__ cbias, const float* __restrict__ Xres,
      float* __restrict__ Y)
{
    constexpr int SS = 32768;
    extern __shared__ __align__(1024) char smem[];
    const uint32_t sb = smem_u32(smem);
    float* sbias = (float*)(smem + 4 * SS);

    const int bm = blockIdx.y * 128;
    const int bn = blockIdx.x * 128;
    const int t = threadIdx.x;
    const int lane = t & 31;
    const int wid = t >> 5;
    const int warp_m = (wid & 1) * 64;
    const int warp_n = (wid >> 1) * 32;

    if (t < 128) sbias[t] = cbias[bn + t];

    uint32_t aOff[4];
    long aG[4], bG[4];
#pragma unroll
    for (int i = 0; i < 4; i++) {
        int id = t + 256 * i;
        int row = id >> 3, ch = id & 7;
        aOff[i] = swz((uint32_t)row, (uint32_t)ch);
        aG[i] = (long)(bm + row) * WW + ch * 4;
        bG[i] = (long)(bn + row) * WW + ch * 4;
    }

#define PG_LOAD(st, f)                                                        \
    {                                                                         \
        const int pl = (f) >> 2;                                              \
        const int kk = (f) & 3;                                               \
        const float* Ab = (pl < 3) ? (S2 + (long)pl * strideP) : T2;          \
        const float* Bb = (pl < 3) ? Ws3 : Wt3;                               \
        const uint32_t s0 = sb + (uint32_t)(st) * SS;                         \
        _Pragma("unroll")                                                     \
        for (int i = 0; i < 4; i++) {                                         \
            CP16(s0 + aOff[i], Ab + aG[i] + kk * 32, 16u);                    \
            CP16(s0 + 16384u + aOff[i], Bb + bG[i] + kk * 32, 16u);           \
        }                                                                     \
    }

    FRAG_DECLS

    float acc[4][4][4], mx[4][4][4];
#pragma unroll
    for (int i = 0; i < 4; i++)
#pragma unroll
        for (int j = 0; j < 4; j++)
#pragma unroll
            for (int q = 0; q < 4; q++) { acc[i][j][q] = 0.f; mx[i][j][q] = -3e38f; }

#pragma unroll
    for (int p = 0; p < 3; p++) { PG_LOAD(p, p); CPCOMMIT(); }
    for (int f = 0; f < 16; f++) {
        CPWAIT2();
        __syncthreads();
        const uint32_t s0 = sb + (uint32_t)(f & 3) * SS;
        MMA3_STAGE(s0);
        if ((f & 3) == 3 && f < 12) {
#pragma unroll
            for (int i = 0; i < 4; i++)
#pragma unroll
                for (int j = 0; j < 4; j++)
#pragma unroll
                    for (int q = 0; q < 4; q++) {
                        mx[i][j][q] = fmaxf(mx[i][j][q], acc[i][j][q]);
                        acc[i][j][q] = 0.f;
                    }
        }
        const int nx = f + 3;
        if (nx < 16) PG_LOAD((nx & 3), nx);
        CPCOMMIT();
    }

    const int mrow = bm + warp_m + (lane >> 2);
#pragma unroll
    for (int i = 0; i < 4; i++) {
        const int m0 = mrow + i * 16;
        const float* X0 = Xres + (long)m0 * HH;
        const float* X8 = X0 + (long)8 * HH;
        float* Y0 = Y + (long)m0 * HH;
        float* Y8 = Y0 + (long)8 * HH;
#pragma unroll
        for (int j = 0; j < 4; j++) {
            const int nb = warp_n + j * 8 + (lane & 3) * 2;
            const int nn = bn + nb;
            float2 x0 = *(const float2*)(X0 + nn);
            float2 x8 = *(const float2*)(X8 + nn);
            float b0 = sbias[nb], b1 = sbias[nb + 1];
            float v0 = acc[i][j][0] + mx[i][j][0] + b0 + x0.x;
            float v1 = acc[i][j][1] + mx[i][j][1] + b1 + x0.y;
            float v2 = acc[i][j][2] + mx[i][j][2] + b0 + x8.x;
            float v3 = acc[i][j][3] + mx[i][j][3] + b1 + x8.y;
            *(float2*)(Y0 + nn) = make_float2(fmaxf(v0, 0.f), fmaxf(v1, 0.f));
            *(float2*)(Y8 + nn) = make_float2(fmaxf(v2, 0.f), fmaxf(v3, 0.f));
        }
    }
#undef PG_LOAD
}

// ---------------- merge per-row key partials into final top-3 indices -------
__global__ void top3_merge(const unsigned long long* __restrict__ ptk,
                           int* __restrict__ idx)
{
    int row = blockIdx.x * 256 + threadIdx.x;
    if (row >= BTN) return;
    int b = row >> 10, r = row & 1023;
    unsigned long long k0 = 0ull, k1 = 0ull, k2 = 0ull;
#pragma unroll
    for (int ct = 0; ct < 8; ct++) {
        size_t o = (((size_t)b * 8 + ct) * TT + r) * 3;
        T3K_INS(ptk[o]); T3K_INS(ptk[o + 1]); T3K_INS(ptk[o + 2]);
    }
    idx[row * 3 + 0] = (int)(~(uint32_t)k0);
    idx[row * 3 + 1] = (int)(~(uint32_t)k1);
    idx[row * 3 + 2] = (int)(~(uint32_t)k2);
}

// ---------------- im2col for backbone grouped conv (groups=4, k=3, pad=1) ----
__global__ void im2col_k3(const float* __restrict__ h, float* __restrict__ xcol)
{
    size_t o = (size_t)blockIdx.x * blockDim.x + threadIdx.x;
    if (o >= (size_t)BTN * FEAT) return;
    int j = (int)(o % FEAT);
    size_t bt = o / FEAT;
    int t = (int)(bt & 1023);
    size_t b = bt >> 10;
    int g = j / 192, r = j % 192, i = r / 3, dt = r % 3;
    int ts = t + dt - 1;
    float v = 0.f;
    if (ts >= 0 && ts < TT) v = h[((b << 10) + ts) * HH + g * 64 + i];
    xcol[o] = v;
}

// ---------------- pack fused B + combined bias for BOTH layers --------------
__global__ void pack_fused2(const float* __restrict__ t1w, const float* __restrict__ t1b,
                            const float* __restrict__ s1w, const float* __restrict__ s1b,
                            const float* __restrict__ t3b, const float* __restrict__ s3b,
                            float* __restrict__ Bf, float* __restrict__ bf,
                            float* __restrict__ cb)
{
    const int l = blockIdx.y;
    const float* t1wl = t1w + (size_t)l * WW * HH;
    const float* t1bl = t1b + (size_t)l * WW;
    const float* s1wl = s1w + (size_t)l * WW * (2 * HH);
    const float* s1bl = s1b + (size_t)l * WW;
    float* B = Bf + (size_t)l * 384 * 256;
    float* bb = bf + (size_t)l * 384;
    int i = blockIdx.x * 256 + threadIdx.x;
    if (i < 384 * 256) {
        int r = i >> 8, c = i & 255;
        float v;
        if (r < 128)      v = t1wl[r * 256 + c];
        else if (r < 256) v = s1wl[(r - 128) * 512 + c];
        else              v = s1wl[(r - 256) * 512 + 256 + c];
        B[i] = v;
    }
    if (i < 384)
        bb[i] = (i < 128) ? t1bl[i] : (i < 256 ? 0.f : s1bl[i - 256]);
    if (i < 256)
        cb[l * 256 + i] = t3b[l * 256 + i] + s3b[l * 256 + i];
}

// ---------------- t2: grouped conv1d (groups=32, 4 in/group, k=3), relu ------
__global__ void t2conv(const float* __restrict__ x, int ldx,
                       const float* __restrict__ w,
                       const float* __restrict__ bias, float* __restrict__ y)
{
    __shared__ float sh[34][WW];
    const int b  = blockIdx.y;
    const int t0 = blockIdx.x * 32;
    const int o  = threadIdx.x;

#pragma unroll 2
    for (int r = 0; r < 34; r++) {
        int ts = t0 - 1 + r;
        sh[r][o] = (ts >= 0 && ts < TT) ? x[(((size_t)b << 10) + ts) * ldx + o] : 0.f;
    }
    __syncthreads();

    float wr[12];
#pragma unroll
    for (int q = 0; q < 12; q++) wr[q] = w[o * 12 + q];
    const float bb = bias[o];
    const int g4 = (o >> 2) << 2;

    for (int tt = 0; tt < 32; tt++) {
        float acc = bb;
#pragma unroll
        for (int i = 0; i < 4; i++)
#pragma unroll
            for (int dt = 0; dt < 3; dt++)
                acc = fmaf(wr[i * 3 + dt], sh[tt + dt][g4 + i], acc);
        y[(((size_t)b << 10) + t0 + tt) * WW + o] = fmaxf(acc, 0.f);
    }
}

// ---------------- per-frame squared L2 norms ----------------
__global__ void rownorm(const float* __restrict__ X, float* __restrict__ xx)
{
    int row = blockIdx.x * 8 + (threadIdx.x >> 5);
    int lane = threadIdx.x & 31;
    const float* p = X + (size_t)row * HH;
    float s = 0.f;
#pragma unroll
    for (int c = lane; c < HH; c += 32) { float v = p[c]; s = fmaf(v, v, s); }
#pragma unroll
    for (int off = 16; off; off >>= 1) s += __shfl_down_sync(0xffffffffu, s, off);
    if (!lane) xx[row] = s;
}

// ---------------- fused s1-epilogue (gather+relu) + grouped s2, plane out ----
__global__ void s1s2(const float* __restrict__ Pn, const float* __restrict__ Pc, int ld,
                     const int* __restrict__ idx, const float* __restrict__ s2w,
                     const float* __restrict__ s2b, float* __restrict__ out)
{
    const int bt = blockIdx.x;
    const int c  = threadIdx.x;
    const int b  = bt >> 10;
    __shared__ float sh[3][WW];
    __shared__ int sidx[3];
    if (c < 3) sidx[c] = idx[bt * 3 + c];
    __syncthreads();

    const float pc = Pc[(size_t)bt * ld + c];
#pragma unroll
    for (int k = 0; k < 3; k++) {
        size_t j = ((size_t)(b << 10) + sidx[k]);
        sh[k][c] = fmaxf(Pn[j * ld + c] + pc, 0.f);
    }
    __syncthreads();

    const float w0 = s2w[c * 4 + 0], w1 = s2w[c * 4 + 1];
    const float w2 = s2w[c * 4 + 2], w3 = s2w[c * 4 + 3];
    const float bb = s2b[c];
    const int gb = (c >> 2) << 2;
#pragma unroll
    for (int k = 0; k < 3; k++) {
        float acc = bb;
        acc = fmaf(w0, sh[k][gb + 0], acc);
        acc = fmaf(w1, sh[k][gb + 1], acc);
        acc = fmaf(w2, sh[k][gb + 2], acc);
        acc = fmaf(w3, sh[k][gb + 3], acc);
        out[((size_t)k * BTN + bt) * WW + c] = fmaxf(acc, 0.f);
    }
}

// ---------------- host side ----------------
static const int SHM = 4 * 32768 + 1024;

template<int TERMS, bool RELU, bool HASBIAS, bool GRAMSYM>
static void launch_mgemm(dim3 grid,
                         const float* A, long sA, int lda,
                         const float* B, long sB, int ldb,
                         const float* bias, int sBias,
                         float* C, long sC, int ldc,
                         int M, int N, int K, int reluN,
                         const float* xx, unsigned long long* ptk)
{
    static bool init = [] {
        cudaFuncSetAttribute(mgemm<TERMS, RELU, HASBIAS, GRAMSYM>,
                             cudaFuncAttributeMaxDynamicSharedMemorySize, SHM);
        return true;
    }();
    (void)init;
    mgemm<TERMS, RELU, HASBIAS, GRAMSYM><<<grid, 256, SHM>>>(
        A, sA, lda, B, sB, ldb, bias, sBias, C, sC, ldc, M, N, K, reluN, xx, ptk);
}

static void tgemm(const float* A, long sA, int lda,
                  const float* B, long sB, int ldb,
                  const float* bias, int sBias,
                  float* C, long sC, int ldc,
                  int M, int N, int K, int batches, bool relu, int reluN,
                  int terms)
{
    dim3 grid((N + 127) / 128, M / 128, batches);
    if (terms == 3) {
        if (relu)
            launch_mgemm<3, true, true, false>(grid, A, sA, lda, B, sB, ldb, bias, sBias,
                                               C, sC, ldc, M, N, K, reluN, nullptr, nullptr);
        else if (bias)
            launch_mgemm<3, false, true, false>(grid, A, sA, lda, B, sB, ldb, bias, sBias,
                                                C, sC, ldc, M, N, K, 0, nullptr, nullptr);
        else
            launch_mgemm<3, false, false, false>(grid, A, sA, lda, B, sB, ldb, nullptr, 0,
                                                 C, sC, ldc, M, N, K, 0, nullptr, nullptr);
    } else {
        launch_mgemm<1, false, true, false>(grid, A, sA, lda, B, sB, ldb, bias, sBias,
                                            C, sC, ldc, M, N, K, 0, nullptr, nullptr);
    }
}

extern "C" void kernel_launch(void* const* d_in, const int* in_sizes, int n_in,
                              void* d_out, int out_size)
{
    const float* x      = (const float*)d_in[0];
    const float* fcin_w = (const float*)d_in[1];
    const float* fcin_b = (const float*)d_in[2];
    const float* conv_w = (const float*)d_in[3];
    const float* conv_b = (const float*)d_in[4];
    const float* t1w    = (const float*)d_in[5];
    const float* t1b    = (const float*)d_in[6];
    const float* t2w    = (const float*)d_in[7];
    const float* t2b    = (const float*)d_in[8];
    const float* t3w    = (const float*)d_in[9];
    const float* t3b    = (const float*)d_in[10];
    const float* s1w    = (const float*)d_in[11];
    const float* s1b    = (const float*)d_in[12];
    const float* s2w    = (const float*)d_in[13];
    const float* s2b    = (const float*)d_in[14];
    const float* s3w    = (const float*)d_in[15];
    const float* s3b    = (const float*)d_in[16];
    const float* fcw    = (const float*)d_in[17];
    const float* fcb    = (const float*)d_in[18];

    void *vp;
    float *p_h0, *p_h1, *p_big, *p_t2, *p_xx, *p_s2, *p_bf, *p_bfb, *p_cb;
    unsigned long long* p_ptk;
    int *p_idx;
    cudaGetSymbolAddress(&vp, g_h0);   p_h0   = (float*)vp;
    cudaGetSymbolAddress(&vp, g_h1);   p_h1   = (float*)vp;
    cudaGetSymbolAddress(&vp, g_big);  p_big  = (float*)vp;
    cudaGetSymbolAddress(&vp, g_t2);   p_t2   = (float*)vp;
    cudaGetSymbolAddress(&vp, g_xx);   p_xx   = (float*)vp;
    cudaGetSymbolAddress(&vp, g_idx);  p_idx  = (int*)vp;
    cudaGetSymbolAddress(&vp, g_s2);   p_s2   = (float*)vp;
    cudaGetSymbolAddress(&vp, g_bf);   p_bf   = (float*)vp;
    cudaGetSymbolAddress(&vp, g_bfb);  p_bfb  = (float*)vp;
    cudaGetSymbolAddress(&vp, g_cb);   p_cb   = (float*)vp;
    cudaGetSymbolAddress(&vp, g_ptk);  p_ptk  = (unsigned long long*)vp;

    // 0) weight packs
    pack_fused2<<<dim3(384, 2), 256>>>(t1w, t1b, s1w, s1b, t3b, s3b, p_bf, p_bfb, p_cb);

    // 1) fc_in + relu -> g_h0
    tgemm(x, 0, FEAT, fcin_w, 0, FEAT, fcin_b, 0, p_h0, 0, HH, BTN, HH, FEAT, 1, true, HH, 3);

    // 2) backbone grouped conv via im2col + 4 batched GEMMs (relu) -> g_h1
    {
        size_t tot = (size_t)BTN * FEAT;
        im2col_k3<<<(unsigned)((tot + 255) / 256), 256>>>(p_h0, p_big);
        tgemm(p_big, 192, FEAT, conv_w, 64 * 192, 192, conv_b, 64,
              p_h1, 64, HH, BTN, 64, 192, 4, true, 64, 3);
    }

    // 3) GCNeXt blocks
    {
        static bool init = [] {
            cudaFuncSetAttribute(pgemm, cudaFuncAttributeMaxDynamicSharedMemorySize, SHM);
            return true;
        }();
        (void)init;
    }
    for (int l = 0; l < LL; l++) {
        const float* X = (l == 0) ? p_h1 : p_h0;
        float*       Y = (l == 0) ? p_h0 : p_h1;
        const float* t3wl = t3w + (size_t)l * HH * WW;
        const float* s3wl = s3w + (size_t)l * HH * WW;

        // fused t1|Pn|Pc GEMM: N=384, relu only on first 128 cols
        tgemm(X, 0, HH, p_bf + (size_t)l * 384 * 256, 0, HH, p_bfb + (size_t)l * 384, 0,
              p_big, 0, 384, BTN, 384, HH, 1, true, 128, 3);

        t2conv<<<dim3(TT / 32, BB), WW>>>(p_big, 384, t2w + (size_t)l * WW * 12,
                                          t2b + (size_t)l * WW, p_t2);

        // kNN graph: symmetric gram with fused branchless top-3
        rownorm<<<BTN / 8, 256>>>(X, p_xx);
        {
            dim3 grid(8, 8, BB);
            launch_mgemm<3, false, false, true>(grid,
                X, (long)TT * HH, HH, X, (long)TT * HH, HH, nullptr, 0,
                nullptr, 0, 0, TT, TT, HH, 0, p_xx, p_ptk);
        }
        top3_merge<<<(BTN + 255) / 256, 256>>>(p_ptk, p_idx);

        // semantic branch: gather -> s2 planes
        s1s2<<<BTN, WW>>>(p_big + 128, p_big + 256, 384, p_idx,
                          s2w + (size_t)l * WW * 4, s2b + (size_t)l * WW, p_s2);

        // fused t3 + s3-max + residual + relu
        pgemm<<<dim3(2, BTN / 128), 256, SHM>>>(
            p_s2, (long)BTN * WW, p_t2, s3wl, t3wl, p_cb + (size_t)l * 256, X, Y);
    }

    // 4) final fc
    tgemm(p_h1, 0, HH, fcw, 0, HH, fcb, 0, (float*)d_out, 0, CC, BTN, CC, HH, 1, false, 0, 1);
}